// round 2
// baseline (speedup 1.0000x reference)
#include <cuda_runtime.h>
#include <math.h>

// Per-row KLD loss between two rotated boxes expressed as 2D Gaussians.
// All 2x2 matrix algebra in closed form; fast-math intrinsics (tolerance 1e-3,
// current accuracy margin ~1e-6).
__device__ __forceinline__ float row_loss(const float* __restrict__ p,
                                          const float* __restrict__ t) {
    // deltas between means
    float dx = p[0] - t[0];
    float dy = p[1] - t[1];

    // pred sigma
    float wp = fminf(fmaxf(p[2], 1e-7f), 1e7f);
    float hp = fminf(fmaxf(p[3], 1e-7f), 1e7f);
    float ap = 0.25f * wp * wp;          // (w/2)^2
    float bp = 0.25f * hp * hp;
    float sp, cp;
    __sincosf(p[4], &sp, &cp);           // |r| < pi/2: MUFU path is accurate
    float cp2 = cp * cp, sp2 = sp * sp;
    float p00 = ap * cp2 + bp * sp2;
    float p11 = ap * sp2 + bp * cp2;
    float p01 = (ap - bp) * sp * cp;

    // target sigma
    float wt = fminf(fmaxf(t[2], 1e-7f), 1e7f);
    float ht = fminf(fmaxf(t[3], 1e-7f), 1e7f);
    float at = 0.25f * wt * wt;
    float bt = 0.25f * ht * ht;
    float st, ct;
    __sincosf(t[4], &st, &ct);
    float ct2 = ct * ct, st2 = st * st;
    float t00 = at * ct2 + bt * st2;
    float t11 = at * st2 + bt * ct2;
    float t01 = (at - bt) * st * ct;

    float det_p = p00 * p11 - p01 * p01;
    float det_t = t00 * t11 - t01 * t01;
    float inv_det_t = __fdividef(1.0f, det_t);

    // term1 = delta^T Sigma_t^{-1} delta
    float term1 = (dx * dx * t11 - 2.0f * dx * dy * t01 + dy * dy * t00) * inv_det_t;
    // tr(Sigma_t^{-1} Sigma_p)
    float tr = (t11 * p00 + t00 * p11 - 2.0f * t01 * p01) * inv_det_t;

    float dis = term1 + tr + __logf(__fdividef(det_t, det_p)) - 2.0f;
    float kl = fmaxf(dis, 1e-6f);
    float L = __logf(1.0f + kl);         // log1p: kl >= 1e-6, f32-exact enough
    // 1 - 1/(1+L) == L/(1+L)  (tau = 1)
    return __fdividef(L, 1.0f + L);
}

// Vectorized: each thread handles 4 rows = 20 floats = 5 float4 loads per input.
__global__ void __launch_bounds__(256, 5)
kld_loss_vec4_kernel(const float4* __restrict__ pred,
                     const float4* __restrict__ targ,
                     float4* __restrict__ out, int n4) {
    int i = blockIdx.x * blockDim.x + threadIdx.x;
    if (i >= n4) return;

    float4 pv[5], tv[5];
#pragma unroll
    for (int k = 0; k < 5; k++) {
        pv[k] = pred[5 * i + k];
        tv[k] = targ[5 * i + k];
    }
    const float* pf = reinterpret_cast<const float*>(pv);
    const float* tf = reinterpret_cast<const float*>(tv);

    float4 r;
    r.x = row_loss(pf + 0,  tf + 0);
    r.y = row_loss(pf + 5,  tf + 5);
    r.z = row_loss(pf + 10, tf + 10);
    r.w = row_loss(pf + 15, tf + 15);
    out[i] = r;
}

// Scalar tail for n % 4 != 0 (not hit for N=4M, kept for safety).
__global__ void kld_loss_tail_kernel(const float* __restrict__ pred,
                                     const float* __restrict__ targ,
                                     float* __restrict__ out,
                                     int start, int n) {
    int i = start + blockIdx.x * blockDim.x + threadIdx.x;
    if (i >= n) return;
    out[i] = row_loss(pred + 5 * i, targ + 5 * i);
}

extern "C" void kernel_launch(void* const* d_in, const int* in_sizes, int n_in,
                              void* d_out, int out_size) {
    const float* pred = (const float*)d_in[0];
    const float* targ = (const float*)d_in[1];
    float* out = (float*)d_out;

    int n = in_sizes[0] / 5;   // number of rows
    int n4 = n / 4;
    int rem_start = n4 * 4;

    if (n4 > 0) {
        const int threads = 256;
        int blocks = (n4 + threads - 1) / threads;
        kld_loss_vec4_kernel<<<blocks, threads>>>(
            (const float4*)pred, (const float4*)targ, (float4*)out, n4);
    }
    if (rem_start < n) {
        int rem = n - rem_start;
        kld_loss_tail_kernel<<<(rem + 127) / 128, 128>>>(pred, targ, out,
                                                         rem_start, n);
    }
}

// round 3
// speedup vs baseline: 1.0077x; 1.0077x over previous
#include <cuda_runtime.h>
#include <math.h>

// Per-row KLD loss between two rotated boxes expressed as 2D Gaussians.
// Fast-math intrinsics: tolerance is 1e-3; measured accuracy margin ~5e-8.
__device__ __forceinline__ float row_loss(const float* __restrict__ p,
                                          const float* __restrict__ t) {
    float dx = p[0] - t[0];
    float dy = p[1] - t[1];

    float wp = fminf(fmaxf(p[2], 1e-7f), 1e7f);
    float hp = fminf(fmaxf(p[3], 1e-7f), 1e7f);
    float ap = 0.25f * wp * wp;
    float bp = 0.25f * hp * hp;
    float sp, cp;
    __sincosf(p[4], &sp, &cp);           // |r| < pi/2: MUFU path accurate
    float cp2 = cp * cp, sp2 = sp * sp;
    float p00 = ap * cp2 + bp * sp2;
    float p11 = ap * sp2 + bp * cp2;
    float p01 = (ap - bp) * sp * cp;

    float wt = fminf(fmaxf(t[2], 1e-7f), 1e7f);
    float ht = fminf(fmaxf(t[3], 1e-7f), 1e7f);
    float at = 0.25f * wt * wt;
    float bt = 0.25f * ht * ht;
    float st, ct;
    __sincosf(t[4], &st, &ct);
    float ct2 = ct * ct, st2 = st * st;
    float t00 = at * ct2 + bt * st2;
    float t11 = at * st2 + bt * ct2;
    float t01 = (at - bt) * st * ct;

    float det_p = p00 * p11 - p01 * p01;
    float det_t = t00 * t11 - t01 * t01;
    float inv_det_t = __fdividef(1.0f, det_t);

    float term1 = (dx * dx * t11 - 2.0f * dx * dy * t01 + dy * dy * t00) * inv_det_t;
    float tr = (t11 * p00 + t00 * p11 - 2.0f * t01 * p01) * inv_det_t;

    float dis = term1 + tr + __logf(__fdividef(det_t, det_p)) - 2.0f;
    float kl = fmaxf(dis, 1e-6f);
    float L = __logf(1.0f + kl);
    return __fdividef(L, 1.0f + L);      // 1 - 1/(1+L), tau = 1
}

// Smem-staged AoS loader: block of 256 threads handles 256 rows.
// 320 float4 per input are loaded lane-consecutively (optimal 4 lines per
// LDG.128 -> minimal L1tex wavefronts), then each thread reads its row from
// smem at word-stride 5 (gcd(5,32)=1 -> bank-conflict-free).
__global__ void __launch_bounds__(256, 6)
kld_loss_staged_kernel(const float4* __restrict__ pred,
                       const float4* __restrict__ targ,
                       float* __restrict__ out) {
    constexpr int ROWS = 256;
    constexpr int NV = ROWS * 5 / 4;     // 320 float4 per input per block
    __shared__ float sp[ROWS * 5];
    __shared__ float st[ROWS * 5];

    int tid = threadIdx.x;
    size_t vbase = (size_t)blockIdx.x * NV;

    // stage loads: iter 0 = all 256 threads, iter 1 = first 64 threads
#pragma unroll
    for (int k = 0; k < 2; k++) {
        int idx = k * 256 + tid;
        if (idx < NV) {
            reinterpret_cast<float4*>(sp)[idx] = pred[vbase + idx];
            reinterpret_cast<float4*>(st)[idx] = targ[vbase + idx];
        }
    }
    __syncthreads();

    float r = row_loss(sp + 5 * tid, st + 5 * tid);
    out[(size_t)blockIdx.x * ROWS + tid] = r;   // coalesced STG.32
}

// Scalar tail for rows not covered by full blocks (not hit for N=4M).
__global__ void kld_loss_tail_kernel(const float* __restrict__ pred,
                                     const float* __restrict__ targ,
                                     float* __restrict__ out,
                                     int start, int n) {
    int i = start + blockIdx.x * blockDim.x + threadIdx.x;
    if (i >= n) return;
    out[i] = row_loss(pred + 5 * i, targ + 5 * i);
}

extern "C" void kernel_launch(void* const* d_in, const int* in_sizes, int n_in,
                              void* d_out, int out_size) {
    const float* pred = (const float*)d_in[0];
    const float* targ = (const float*)d_in[1];
    float* out = (float*)d_out;

    int n = in_sizes[0] / 5;       // number of rows
    int full_blocks = n / 256;     // 15625 for N=4M
    int rem_start = full_blocks * 256;

    if (full_blocks > 0) {
        kld_loss_staged_kernel<<<full_blocks, 256>>>(
            (const float4*)pred, (const float4*)targ, out);
    }
    if (rem_start < n) {
        int rem = n - rem_start;
        kld_loss_tail_kernel<<<(rem + 127) / 128, 128>>>(pred, targ, out,
                                                         rem_start, n);
    }
}